// round 1
// baseline (speedup 1.0000x reference)
#include <cuda_runtime.h>
#include <cuda_bf16.h>
#include <math.h>

// Problem constants (match reference)
#define N_NODES   100000
#define N_EDGES   600000
#define N_GRAPHS  1000
#define VOCAB     10000
#define D         128          // EMB == HID

// ---------------- scratch (static device allocations are allowed) ----------
__device__ float g_x[N_NODES * D];      // node features
__device__ float g_agg[N_NODES * D];    // x + sum of neighbors (per layer)
__device__ float g_embT[VOCAB * D];     // emb @ conv_w1[0]
__device__ float g_pool[N_GRAPHS * D];  // per-graph sums

// ---------------- zero the pool sums ---------------------------------------
__global__ void zero_pool_kernel() {
    for (int i = blockIdx.x * blockDim.x + threadIdx.x; i < N_GRAPHS * D;
         i += gridDim.x * blockDim.x)
        g_pool[i] = 0.0f;
}

// ---------------- gather: x = agg = embT[x_idx] (warp per node) ------------
__global__ void gather_kernel(const int* __restrict__ x_idx, int nNodes) {
    int gid = blockIdx.x * blockDim.x + threadIdx.x;
    int node = gid >> 5, c = gid & 31;
    if (node >= nNodes) return;
    int row = x_idx[node];
    float4 v = ((const float4*)g_embT)[row * 32 + c];
    ((float4*)g_x)[node * 32 + c]   = v;
    ((float4*)g_agg)[node * 32 + c] = v;
}

// ---------------- scatter: agg[dst] += x[src] (warp per edge, v4 red) ------
__global__ void scatter_kernel(const float* __restrict__ xin,
                               float* __restrict__ agg,
                               const int* __restrict__ src,
                               const int* __restrict__ dst, int nE) {
    int gid = blockIdx.x * blockDim.x + threadIdx.x;
    int e = gid >> 5, c = gid & 31;
    if (e >= nE) return;
    int s = src[e], d = dst[e];
    float4 v = ((const float4*)xin)[s * 32 + c];
    float* p = agg + d * D + c * 4;
    asm volatile("red.global.add.v4.f32 [%0], {%1, %2, %3, %4};"
                 :: "l"(p), "f"(v.x), "f"(v.y), "f"(v.z), "f"(v.w)
                 : "memory");
}

// ---------------- pool: g_pool[batch[i]] += x[i] ---------------------------
__global__ void pool_kernel(const int* __restrict__ batch, int nNodes) {
    int gid = blockIdx.x * blockDim.x + threadIdx.x;
    int node = gid >> 5, c = gid & 31;
    if (node >= nNodes) return;
    int b = batch[node];
    float4 v = ((const float4*)g_x)[node * 32 + c];
    float* p = g_pool + b * D + c * 4;
    asm volatile("red.global.add.v4.f32 [%0], {%1, %2, %3, %4};"
                 :: "l"(p), "f"(v.x), "f"(v.y), "f"(v.z), "f"(v.w)
                 : "memory");
}

// ---------------- fused MLP -------------------------------------------------
// MODE 0: out = x @ w2                             (no bias / no relu)
// MODE 1: h = relu(x + b1);      out = relu(h @ w2 + b2)
// MODE 2: h = relu(x @ w1 + b1); out = relu(h @ w2 + b2)
// 64 rows per CTA, 256 threads; weights + tile in SMEM; intermediate h
// overwrites the x tile in SMEM. out2 (optional) gets a second copy of out.
#define TM 64
#define MLP_THREADS 256

__device__ __forceinline__ void gemm_phase(const float* __restrict__ ws,
                                           const float* __restrict__ xs,
                                           int rg, int c0, float acc[8][4]) {
    for (int k0 = 0; k0 < D; k0 += 4) {
        float4 w0 = *(const float4*)(ws + (k0 + 0) * D + c0);
        float4 w1 = *(const float4*)(ws + (k0 + 1) * D + c0);
        float4 w2 = *(const float4*)(ws + (k0 + 2) * D + c0);
        float4 w3 = *(const float4*)(ws + (k0 + 3) * D + c0);
#pragma unroll
        for (int j = 0; j < 8; ++j) {
            float4 xv = *(const float4*)(xs + (rg * 8 + j) * D + k0);
            acc[j][0] += xv.x * w0.x + xv.y * w1.x + xv.z * w2.x + xv.w * w3.x;
            acc[j][1] += xv.x * w0.y + xv.y * w1.y + xv.z * w2.y + xv.w * w3.y;
            acc[j][2] += xv.x * w0.z + xv.y * w1.z + xv.z * w2.z + xv.w * w3.z;
            acc[j][3] += xv.x * w0.w + xv.y * w1.w + xv.z * w2.w + xv.w * w3.w;
        }
    }
}

template <int MODE>
__global__ void __launch_bounds__(MLP_THREADS, 1)
mlp_kernel(const float* __restrict__ x, const float* __restrict__ w1,
           const float* __restrict__ b1, const float* __restrict__ w2,
           const float* __restrict__ b2, float* __restrict__ out,
           float* __restrict__ out2, int nRows) {
    extern __shared__ float sm[];
    float* w2s = sm;                                         // 16384 floats
    float* w1s = sm + 16384;                                 // 16384 (MODE 2)
    float* xs  = (MODE == 2) ? sm + 32768 : sm + 16384;      // 64*128 floats

    const int tid = threadIdx.x;

    // cooperative weight loads
    for (int i = tid; i < (D * D) / 4; i += MLP_THREADS)
        ((float4*)w2s)[i] = ((const float4*)w2)[i];
    if (MODE == 2)
        for (int i = tid; i < (D * D) / 4; i += MLP_THREADS)
            ((float4*)w1s)[i] = ((const float4*)w1)[i];

    const int row0 = blockIdx.x * TM;

    // load x tile (+ optional bias+relu transform for MODE 1)
    for (int i = tid; i < TM * 32; i += MLP_THREADS) {
        int r = row0 + (i >> 5);
        float4 v = make_float4(0.f, 0.f, 0.f, 0.f);
        if (r < nRows) v = ((const float4*)x)[r * 32 + (i & 31)];
        if (MODE == 1) {
            float4 bv = ((const float4*)b1)[i & 31];
            v.x = fmaxf(v.x + bv.x, 0.f);
            v.y = fmaxf(v.y + bv.y, 0.f);
            v.z = fmaxf(v.z + bv.z, 0.f);
            v.w = fmaxf(v.w + bv.w, 0.f);
        }
        ((float4*)xs)[i] = v;
    }
    __syncthreads();

    const int c0 = (tid & 31) * 4;   // 4 output columns per thread
    const int rg = tid >> 5;         // 8 row-groups of 8 rows each
    float acc[8][4];

    if (MODE == 2) {
        // phase 1: h = relu(x @ w1 + b1) -> overwrite xs
        float4 b1v = ((const float4*)b1)[tid & 31];
#pragma unroll
        for (int j = 0; j < 8; ++j) {
            acc[j][0] = b1v.x; acc[j][1] = b1v.y;
            acc[j][2] = b1v.z; acc[j][3] = b1v.w;
        }
        gemm_phase(w1s, xs, rg, c0, acc);
        __syncthreads();
#pragma unroll
        for (int j = 0; j < 8; ++j) {
            float4 h;
            h.x = fmaxf(acc[j][0], 0.f); h.y = fmaxf(acc[j][1], 0.f);
            h.z = fmaxf(acc[j][2], 0.f); h.w = fmaxf(acc[j][3], 0.f);
            *(float4*)(xs + (rg * 8 + j) * D + c0) = h;
        }
        __syncthreads();
    }

    // phase 2: out = (relu)(h @ w2 + b2)
    if (MODE == 0) {
#pragma unroll
        for (int j = 0; j < 8; ++j)
            acc[j][0] = acc[j][1] = acc[j][2] = acc[j][3] = 0.f;
    } else {
        float4 b2v = ((const float4*)b2)[tid & 31];
#pragma unroll
        for (int j = 0; j < 8; ++j) {
            acc[j][0] = b2v.x; acc[j][1] = b2v.y;
            acc[j][2] = b2v.z; acc[j][3] = b2v.w;
        }
    }
    gemm_phase(w2s, xs, rg, c0, acc);

#pragma unroll
    for (int j = 0; j < 8; ++j) {
        int r = row0 + rg * 8 + j;
        if (r >= nRows) continue;
        float4 o;
        if (MODE == 0) {
            o.x = acc[j][0]; o.y = acc[j][1]; o.z = acc[j][2]; o.w = acc[j][3];
        } else {
            o.x = fmaxf(acc[j][0], 0.f); o.y = fmaxf(acc[j][1], 0.f);
            o.z = fmaxf(acc[j][2], 0.f); o.w = fmaxf(acc[j][3], 0.f);
        }
        ((float4*)out)[r * 32 + (tid & 31)] = o;
        if (out2) ((float4*)out2)[r * 32 + (tid & 31)] = o;
    }
}

// ---------------- classifier: mean pool -> MLP -> softmax ------------------
__global__ void classifier_kernel(const int* __restrict__ batch, int nNodes,
                                  const float* __restrict__ w1,
                                  const float* __restrict__ b1,
                                  const float* __restrict__ w2,
                                  const float* __restrict__ b2,
                                  float* __restrict__ out) {
    __shared__ float gs[D];
    __shared__ float hs[64];
    __shared__ float cnt_s;
    const int b = blockIdx.x;
    const int t = threadIdx.x;

    if (t == 0) {
        // node count for graph b via binary search on sorted batch
        int lo = 0, hi = nNodes;
        while (lo < hi) { int m = (lo + hi) >> 1; if (batch[m] < b) lo = m + 1; else hi = m; }
        int start = lo;
        lo = start; hi = nNodes;
        while (lo < hi) { int m = (lo + hi) >> 1; if (batch[m] <= b) lo = m + 1; else hi = m; }
        cnt_s = fmaxf((float)(lo - start), 1.0f);
    }
    __syncthreads();

    gs[t] = g_pool[b * D + t] / cnt_s;
    __syncthreads();

    if (t < 64) {
        float h = b1[t];
#pragma unroll 8
        for (int k = 0; k < D; ++k) h += gs[k] * w1[k * 64 + t];
        hs[t] = fmaxf(h, 0.f);
    }
    __syncthreads();

    if (t == 0) {
        float o0 = b2[0], o1 = b2[1];
#pragma unroll 8
        for (int j = 0; j < 64; ++j) {
            o0 += hs[j] * w2[2 * j];
            o1 += hs[j] * w2[2 * j + 1];
        }
        float m = fmaxf(o0, o1);
        float e0 = expf(o0 - m), e1 = expf(o1 - m);
        float s = e0 + e1;
        out[2 * b]     = e0 / s;
        out[2 * b + 1] = e1 / s;
    }
}

// ---------------------------------------------------------------------------
extern "C" void kernel_launch(void* const* d_in, const int* in_sizes, int n_in,
                              void* d_out, int out_size) {
    const int*   x_idx   = (const int*)d_in[0];
    const int*   edge    = (const int*)d_in[1];
    const int*   batch   = (const int*)d_in[2];
    const float* emb     = (const float*)d_in[3];
    const float* conv_w1 = (const float*)d_in[4];
    const float* conv_b1 = (const float*)d_in[5];
    const float* conv_w2 = (const float*)d_in[6];
    const float* conv_b2 = (const float*)d_in[7];
    const float* mlp_w1  = (const float*)d_in[8];
    const float* mlp_b1  = (const float*)d_in[9];
    const float* mlp_w2  = (const float*)d_in[10];
    const float* mlp_b2  = (const float*)d_in[11];
    float* out = (float*)d_out;

    const int nNodes = in_sizes[0];
    const int nEdges = in_sizes[1] / 2;
    const int nVocab = in_sizes[3] / D;
    const int* src = edge;
    const int* dst = edge + nEdges;

    float *px, *pagg, *pembT;
    cudaGetSymbolAddress((void**)&px,   g_x);
    cudaGetSymbolAddress((void**)&pagg, g_agg);
    cudaGetSymbolAddress((void**)&pembT, g_embT);

    const size_t smem_small = (16384 + TM * D) * sizeof(float);   // 98304 B
    const size_t smem_big   = (32768 + TM * D) * sizeof(float);   // 163840 B
    cudaFuncSetAttribute(mlp_kernel<0>, cudaFuncAttributeMaxDynamicSharedMemorySize, (int)smem_small);
    cudaFuncSetAttribute(mlp_kernel<1>, cudaFuncAttributeMaxDynamicSharedMemorySize, (int)smem_small);
    cudaFuncSetAttribute(mlp_kernel<2>, cudaFuncAttributeMaxDynamicSharedMemorySize, (int)smem_big);

    const int nodeTiles = (nNodes + TM - 1) / TM;
    const int embTiles  = (nVocab + TM - 1) / TM;
    const int gatherBlocks  = (nNodes * 32 + 255) / 256;
    const int scatterBlocks = (nEdges * 32 + 255) / 256;

    zero_pool_kernel<<<500, 256>>>();

    // embT = emb @ conv_w1[0]
    mlp_kernel<0><<<embTiles, MLP_THREADS, smem_small>>>(
        emb, nullptr, nullptr, conv_w1, nullptr, pembT, nullptr, nVocab);

    // layer 0: gather transformed embeddings, aggregate, then relu(.+b1)@w2
    gather_kernel<<<gatherBlocks, 256>>>(x_idx, nNodes);
    scatter_kernel<<<scatterBlocks, 256>>>(px, pagg, src, dst, nEdges);
    mlp_kernel<1><<<nodeTiles, MLP_THREADS, smem_small>>>(
        pagg, nullptr, conv_b1, conv_w2, conv_b2, px, pagg, nNodes);

    // layers 1, 2
    for (int L = 1; L < 3; ++L) {
        scatter_kernel<<<scatterBlocks, 256>>>(px, pagg, src, dst, nEdges);
        float* out2 = (L == 2) ? nullptr : pagg;
        mlp_kernel<2><<<nodeTiles, MLP_THREADS, smem_big>>>(
            pagg, conv_w1 + L * D * D, conv_b1 + L * D,
            conv_w2 + L * D * D, conv_b2 + L * D, px, out2, nNodes);
    }

    // mean pool + classifier + softmax
    pool_kernel<<<gatherBlocks, 256>>>(batch, nNodes);
    classifier_kernel<<<N_GRAPHS, D>>>(batch, nNodes, mlp_w1, mlp_b1, mlp_w2,
                                       mlp_b2, out);
}

// round 2
// speedup vs baseline: 1.4741x; 1.4741x over previous
#include <cuda_runtime.h>
#include <cuda_bf16.h>
#include <math.h>
#include <stdint.h>

// Problem constants (match reference)
#define N_NODES   100000
#define N_EDGES   600000
#define N_GRAPHS  1000
#define VOCAB     10000
#define D         128          // EMB == HID
#define SA        136          // padded smem row stride (bf16 elems) -> conflict-free
#define TM        128          // rows per MLP CTA

// ---------------- scratch -------------------------------------------------
__device__ float g_x[N_NODES * D];
__device__ float g_agg[N_NODES * D];
__device__ float g_embT[VOCAB * D];
__device__ float g_pool[N_GRAPHS * D];
// split-bf16, transposed ([n][k]) padded weights: mats 0..2 = conv_w1[L], 3..5 = conv_w2[L]
__device__ __nv_bfloat16 g_wh[6][D * SA];
__device__ __nv_bfloat16 g_wl[6][D * SA];

// ---------------- helpers -------------------------------------------------
__device__ __forceinline__ uint32_t pack_bf16(float a, float b) {
    __nv_bfloat162 t;
    t.x = __float2bfloat16_rn(a);
    t.y = __float2bfloat16_rn(b);
    return *(uint32_t*)&t;
}

__device__ __forceinline__ void mma16816(float* d, uint32_t a0, uint32_t a1,
                                         uint32_t a2, uint32_t a3,
                                         uint32_t b0, uint32_t b1) {
    asm volatile(
        "mma.sync.aligned.m16n8k16.row.col.f32.bf16.bf16.f32 "
        "{%0,%1,%2,%3}, {%4,%5,%6,%7}, {%8,%9}, {%0,%1,%2,%3};\n"
        : "+f"(d[0]), "+f"(d[1]), "+f"(d[2]), "+f"(d[3])
        : "r"(a0), "r"(a1), "r"(a2), "r"(a3), "r"(b0), "r"(b1));
}

// ---------------- weight prep: split + transpose --------------------------
__global__ void prep_weights(const float* __restrict__ w1,
                             const float* __restrict__ w2) {
    int i = blockIdx.x * blockDim.x + threadIdx.x;
    if (i >= 6 * D * D) return;
    int m = i / (D * D), kn = i % (D * D);
    int k = kn / D, n = kn % D;
    float v = (m < 3) ? w1[m * D * D + kn] : w2[(m - 3) * D * D + kn];
    __nv_bfloat16 h = __float2bfloat16_rn(v);
    __nv_bfloat16 l = __float2bfloat16_rn(v - __bfloat162float(h));
    g_wh[m][n * SA + k] = h;
    g_wl[m][n * SA + k] = l;
}

// ---------------- zero the pool sums --------------------------------------
__global__ void zero_pool_kernel() {
    for (int i = blockIdx.x * blockDim.x + threadIdx.x; i < N_GRAPHS * D;
         i += gridDim.x * blockDim.x)
        g_pool[i] = 0.0f;
}

// ---------------- gather: x = agg = embT[x_idx] ---------------------------
__global__ void gather_kernel(const int* __restrict__ x_idx, int nNodes) {
    int gid = blockIdx.x * blockDim.x + threadIdx.x;
    int node = gid >> 5, c = gid & 31;
    if (node >= nNodes) return;
    int row = x_idx[node];
    float4 v = ((const float4*)g_embT)[row * 32 + c];
    ((float4*)g_x)[node * 32 + c]   = v;
    ((float4*)g_agg)[node * 32 + c] = v;
}

// ---------------- scatter: agg[dst] += x[src] -----------------------------
__global__ void scatter_kernel(const float* __restrict__ xin,
                               float* __restrict__ agg,
                               const int* __restrict__ src,
                               const int* __restrict__ dst, int nE) {
    int gid = blockIdx.x * blockDim.x + threadIdx.x;
    int e = gid >> 5, c = gid & 31;
    if (e >= nE) return;
    int s = src[e], d = dst[e];
    float4 v = ((const float4*)xin)[s * 32 + c];
    float* p = agg + d * D + c * 4;
    asm volatile("red.global.add.v4.f32 [%0], {%1, %2, %3, %4};"
                 :: "l"(p), "f"(v.x), "f"(v.y), "f"(v.z), "f"(v.w)
                 : "memory");
}

// ---------------- pool ----------------------------------------------------
__global__ void pool_kernel(const int* __restrict__ batch, int nNodes) {
    int gid = blockIdx.x * blockDim.x + threadIdx.x;
    int node = gid >> 5, c = gid & 31;
    if (node >= nNodes) return;
    int b = batch[node];
    float4 v = ((const float4*)g_x)[node * 32 + c];
    float* p = g_pool + b * D + c * 4;
    asm volatile("red.global.add.v4.f32 [%0], {%1, %2, %3, %4};"
                 :: "l"(p), "f"(v.x), "f"(v.y), "f"(v.z), "f"(v.w)
                 : "memory");
}

// ---------------- split-bf16 tensor-core GEMM phase -----------------------
// acc[mt][nt][0..3] += A(128xK=128) @ B(K x 128) for this warp's 64x32 patch.
__device__ __forceinline__ void gemm_mma(const __nv_bfloat16* __restrict__ Ah,
                                         const __nv_bfloat16* __restrict__ Al,
                                         const __nv_bfloat16* __restrict__ Bh,
                                         const __nv_bfloat16* __restrict__ Bl,
                                         int R0, int N0, int gr, int gc,
                                         float (&acc)[4][4][4]) {
#pragma unroll
    for (int k0 = 0; k0 < D; k0 += 16) {
        uint32_t bh[4][2], bl[4][2];
#pragma unroll
        for (int nt = 0; nt < 4; ++nt) {
            int n = N0 + nt * 8 + gr;
            bh[nt][0] = *(const uint32_t*)(Bh + n * SA + k0 + gc);
            bh[nt][1] = *(const uint32_t*)(Bh + n * SA + k0 + 8 + gc);
            bl[nt][0] = *(const uint32_t*)(Bl + n * SA + k0 + gc);
            bl[nt][1] = *(const uint32_t*)(Bl + n * SA + k0 + 8 + gc);
        }
#pragma unroll
        for (int mt = 0; mt < 4; ++mt) {
            int r = R0 + mt * 16 + gr;
            uint32_t a0 = *(const uint32_t*)(Ah + r * SA + k0 + gc);
            uint32_t a1 = *(const uint32_t*)(Ah + (r + 8) * SA + k0 + gc);
            uint32_t a2 = *(const uint32_t*)(Ah + r * SA + k0 + 8 + gc);
            uint32_t a3 = *(const uint32_t*)(Ah + (r + 8) * SA + k0 + 8 + gc);
            uint32_t l0 = *(const uint32_t*)(Al + r * SA + k0 + gc);
            uint32_t l1 = *(const uint32_t*)(Al + (r + 8) * SA + k0 + gc);
            uint32_t l2 = *(const uint32_t*)(Al + r * SA + k0 + 8 + gc);
            uint32_t l3 = *(const uint32_t*)(Al + (r + 8) * SA + k0 + 8 + gc);
#pragma unroll
            for (int nt = 0; nt < 4; ++nt) {
                mma16816(acc[mt][nt], a0, a1, a2, a3, bh[nt][0], bh[nt][1]);
                mma16816(acc[mt][nt], a0, a1, a2, a3, bl[nt][0], bl[nt][1]);
                mma16816(acc[mt][nt], l0, l1, l2, l3, bh[nt][0], bh[nt][1]);
            }
        }
    }
}

// ---------------- fused MLP (tensor cores) --------------------------------
// MODE 0: out = x @ W[w2_id]                        (no bias / no relu)
// MODE 1: h = relu(x + b1);      out = relu(h @ W[w2_id] + b2)
// MODE 2: h = relu(x @ W[w1_id] + b1); out = relu(h @ W[w2_id] + b2)
template <int MODE>
__global__ void __launch_bounds__(256, 1)
mlp_mma(const float* __restrict__ x, int w1_id, int w2_id,
        const float* __restrict__ b1, const float* __restrict__ b2,
        float* __restrict__ out, float* __restrict__ out2, int nRows) {
    extern __shared__ __nv_bfloat16 sm[];
    __nv_bfloat16* Ah  = sm;
    __nv_bfloat16* Al  = sm + D * SA;
    __nv_bfloat16* W2h = sm + 2 * D * SA;
    __nv_bfloat16* W2l = sm + 3 * D * SA;
    __nv_bfloat16* W1h = sm + 4 * D * SA;   // MODE 2 only
    __nv_bfloat16* W1l = sm + 5 * D * SA;

    const int tid  = threadIdx.x;
    const int lane = tid & 31, wid = tid >> 5;
    const int R0 = (wid >> 2) * 64, N0 = (wid & 3) * 32;
    const int gr = lane >> 2, gc = (lane & 3) * 2;
    const int row0 = blockIdx.x * TM;

    // stage weights (already split/transposed/padded in global)
    {
        const uint32_t* s2h = (const uint32_t*)g_wh[w2_id];
        const uint32_t* s2l = (const uint32_t*)g_wl[w2_id];
        for (int i = tid; i < D * SA / 2; i += 256) {
            ((uint32_t*)W2h)[i] = s2h[i];
            ((uint32_t*)W2l)[i] = s2l[i];
        }
        if (MODE == 2) {
            const uint32_t* s1h = (const uint32_t*)g_wh[w1_id];
            const uint32_t* s1l = (const uint32_t*)g_wl[w1_id];
            for (int i = tid; i < D * SA / 2; i += 256) {
                ((uint32_t*)W1h)[i] = s1h[i];
                ((uint32_t*)W1l)[i] = s1l[i];
            }
        }
    }

    // load + (MODE1: bias+relu) + split-convert A tile
    for (int i = tid; i < TM * 32; i += 256) {
        int r = i >> 5, c4 = (i & 31) * 4;
        float4 v = make_float4(0.f, 0.f, 0.f, 0.f);
        if (row0 + r < nRows) v = *(const float4*)(x + (size_t)(row0 + r) * D + c4);
        if (MODE == 1) {
            float4 bv = *(const float4*)(b1 + c4);
            v.x = fmaxf(v.x + bv.x, 0.f); v.y = fmaxf(v.y + bv.y, 0.f);
            v.z = fmaxf(v.z + bv.z, 0.f); v.w = fmaxf(v.w + bv.w, 0.f);
        }
        __nv_bfloat16 h0 = __float2bfloat16_rn(v.x), h1 = __float2bfloat16_rn(v.y);
        __nv_bfloat16 h2 = __float2bfloat16_rn(v.z), h3 = __float2bfloat16_rn(v.w);
        *(uint32_t*)(Ah + r * SA + c4)     = pack_bf16(v.x, v.y);
        *(uint32_t*)(Ah + r * SA + c4 + 2) = pack_bf16(v.z, v.w);
        *(uint32_t*)(Al + r * SA + c4) =
            pack_bf16(v.x - __bfloat162float(h0), v.y - __bfloat162float(h1));
        *(uint32_t*)(Al + r * SA + c4 + 2) =
            pack_bf16(v.z - __bfloat162float(h2), v.w - __bfloat162float(h3));
    }
    __syncthreads();

    float acc[4][4][4];

    if (MODE == 2) {
        // phase 1: h = relu(x @ W1 + b1), keep in SMEM (overwrite A tiles)
#pragma unroll
        for (int nt = 0; nt < 4; ++nt) {
            float bb0 = b1[N0 + nt * 8 + gc], bb1 = b1[N0 + nt * 8 + gc + 1];
#pragma unroll
            for (int mt = 0; mt < 4; ++mt) {
                acc[mt][nt][0] = bb0; acc[mt][nt][1] = bb1;
                acc[mt][nt][2] = bb0; acc[mt][nt][3] = bb1;
            }
        }
        gemm_mma(Ah, Al, W1h, W1l, R0, N0, gr, gc, acc);
        __syncthreads();
#pragma unroll
        for (int mt = 0; mt < 4; ++mt) {
#pragma unroll
            for (int nt = 0; nt < 4; ++nt) {
                int r = R0 + mt * 16 + gr, c = N0 + nt * 8 + gc;
                float v0 = fmaxf(acc[mt][nt][0], 0.f), v1 = fmaxf(acc[mt][nt][1], 0.f);
                float v2 = fmaxf(acc[mt][nt][2], 0.f), v3 = fmaxf(acc[mt][nt][3], 0.f);
                __nv_bfloat16 p0 = __float2bfloat16_rn(v0), p1 = __float2bfloat16_rn(v1);
                __nv_bfloat16 p2 = __float2bfloat16_rn(v2), p3 = __float2bfloat16_rn(v3);
                *(uint32_t*)(Ah + r * SA + c)       = pack_bf16(v0, v1);
                *(uint32_t*)(Ah + (r + 8) * SA + c) = pack_bf16(v2, v3);
                *(uint32_t*)(Al + r * SA + c) =
                    pack_bf16(v0 - __bfloat162float(p0), v1 - __bfloat162float(p1));
                *(uint32_t*)(Al + (r + 8) * SA + c) =
                    pack_bf16(v2 - __bfloat162float(p2), v3 - __bfloat162float(p3));
            }
        }
        __syncthreads();
    }

    // phase 2: out = (relu)(h @ W2 + b2)
    if (MODE == 0) {
#pragma unroll
        for (int mt = 0; mt < 4; ++mt)
#pragma unroll
            for (int nt = 0; nt < 4; ++nt)
                acc[mt][nt][0] = acc[mt][nt][1] = acc[mt][nt][2] = acc[mt][nt][3] = 0.f;
    } else {
#pragma unroll
        for (int nt = 0; nt < 4; ++nt) {
            float bb0 = b2[N0 + nt * 8 + gc], bb1 = b2[N0 + nt * 8 + gc + 1];
#pragma unroll
            for (int mt = 0; mt < 4; ++mt) {
                acc[mt][nt][0] = bb0; acc[mt][nt][1] = bb1;
                acc[mt][nt][2] = bb0; acc[mt][nt][3] = bb1;
            }
        }
    }
    gemm_mma(Ah, Al, W2h, W2l, R0, N0, gr, gc, acc);

#pragma unroll
    for (int mt = 0; mt < 4; ++mt) {
#pragma unroll
        for (int nt = 0; nt < 4; ++nt) {
            int r = row0 + R0 + mt * 16 + gr;
            int c = N0 + nt * 8 + gc;
            float v0 = acc[mt][nt][0], v1 = acc[mt][nt][1];
            float v2 = acc[mt][nt][2], v3 = acc[mt][nt][3];
            if (MODE != 0) {
                v0 = fmaxf(v0, 0.f); v1 = fmaxf(v1, 0.f);
                v2 = fmaxf(v2, 0.f); v3 = fmaxf(v3, 0.f);
            }
            if (r < nRows) {
                *(float2*)(out + (size_t)r * D + c) = make_float2(v0, v1);
                if (out2) *(float2*)(out2 + (size_t)r * D + c) = make_float2(v0, v1);
            }
            if (r + 8 < nRows) {
                *(float2*)(out + (size_t)(r + 8) * D + c) = make_float2(v2, v3);
                if (out2) *(float2*)(out2 + (size_t)(r + 8) * D + c) = make_float2(v2, v3);
            }
        }
    }
}

// ---------------- classifier: mean pool -> MLP -> softmax -----------------
__global__ void classifier_kernel(const int* __restrict__ batch, int nNodes,
                                  const float* __restrict__ w1,
                                  const float* __restrict__ b1,
                                  const float* __restrict__ w2,
                                  const float* __restrict__ b2,
                                  float* __restrict__ out) {
    __shared__ float gs[D];
    __shared__ float hs[64];
    __shared__ float cnt_s;
    const int b = blockIdx.x;
    const int t = threadIdx.x;

    if (t == 0) {
        int lo = 0, hi = nNodes;
        while (lo < hi) { int m = (lo + hi) >> 1; if (batch[m] < b) lo = m + 1; else hi = m; }
        int start = lo;
        lo = start; hi = nNodes;
        while (lo < hi) { int m = (lo + hi) >> 1; if (batch[m] <= b) lo = m + 1; else hi = m; }
        cnt_s = fmaxf((float)(lo - start), 1.0f);
    }
    __syncthreads();

    gs[t] = g_pool[b * D + t] / cnt_s;
    __syncthreads();

    if (t < 64) {
        float h = b1[t];
#pragma unroll 8
        for (int k = 0; k < D; ++k) h += gs[k] * w1[k * 64 + t];
        hs[t] = fmaxf(h, 0.f);
    }
    __syncthreads();

    if (t == 0) {
        float o0 = b2[0], o1 = b2[1];
#pragma unroll 8
        for (int j = 0; j < 64; ++j) {
            o0 += hs[j] * w2[2 * j];
            o1 += hs[j] * w2[2 * j + 1];
        }
        float m = fmaxf(o0, o1);
        float e0 = expf(o0 - m), e1 = expf(o1 - m);
        float s = e0 + e1;
        out[2 * b]     = e0 / s;
        out[2 * b + 1] = e1 / s;
    }
}

// ---------------------------------------------------------------------------
extern "C" void kernel_launch(void* const* d_in, const int* in_sizes, int n_in,
                              void* d_out, int out_size) {
    const int*   x_idx   = (const int*)d_in[0];
    const int*   edge    = (const int*)d_in[1];
    const int*   batch   = (const int*)d_in[2];
    const float* emb     = (const float*)d_in[3];
    const float* conv_w1 = (const float*)d_in[4];
    const float* conv_b1 = (const float*)d_in[5];
    const float* conv_w2 = (const float*)d_in[6];
    const float* conv_b2 = (const float*)d_in[7];
    const float* mlp_w1  = (const float*)d_in[8];
    const float* mlp_b1  = (const float*)d_in[9];
    const float* mlp_w2  = (const float*)d_in[10];
    const float* mlp_b2  = (const float*)d_in[11];
    float* out = (float*)d_out;

    const int nNodes = in_sizes[0];
    const int nEdges = in_sizes[1] / 2;
    const int nVocab = in_sizes[3] / D;
    const int* src = edge;
    const int* dst = edge + nEdges;

    float *px, *pagg, *pembT;
    cudaGetSymbolAddress((void**)&px,    g_x);
    cudaGetSymbolAddress((void**)&pagg,  g_agg);
    cudaGetSymbolAddress((void**)&pembT, g_embT);

    const size_t smem4 = 4 * D * SA * sizeof(__nv_bfloat16);   // 139264
    const size_t smem6 = 6 * D * SA * sizeof(__nv_bfloat16);   // 208896
    static int configured = 0;
    cudaFuncSetAttribute(mlp_mma<0>, cudaFuncAttributeMaxDynamicSharedMemorySize, (int)smem4);
    cudaFuncSetAttribute(mlp_mma<1>, cudaFuncAttributeMaxDynamicSharedMemorySize, (int)smem4);
    cudaFuncSetAttribute(mlp_mma<2>, cudaFuncAttributeMaxDynamicSharedMemorySize, (int)smem6);
    (void)configured;

    const int nodeTiles = (nNodes + TM - 1) / TM;
    const int embTiles  = (nVocab + TM - 1) / TM;
    const int gatherBlocks  = (nNodes * 32 + 255) / 256;
    const int scatterBlocks = (nEdges * 32 + 255) / 256;

    zero_pool_kernel<<<500, 256>>>();
    prep_weights<<<(6 * D * D + 255) / 256, 256>>>(conv_w1, conv_w2);

    // embT = emb @ conv_w1[0]   (mat id 0)
    mlp_mma<0><<<embTiles, 256, smem4>>>(emb, -1, 0, nullptr, nullptr,
                                         pembT, nullptr, nVocab);

    // layer 0
    gather_kernel<<<gatherBlocks, 256>>>(x_idx, nNodes);
    scatter_kernel<<<scatterBlocks, 256>>>(px, pagg, src, dst, nEdges);
    mlp_mma<1><<<nodeTiles, 256, smem4>>>(pagg, -1, 3, conv_b1, conv_b2,
                                          px, pagg, nNodes);

    // layers 1, 2
    for (int L = 1; L < 3; ++L) {
        scatter_kernel<<<scatterBlocks, 256>>>(px, pagg, src, dst, nEdges);
        float* out2 = (L == 2) ? nullptr : pagg;
        mlp_mma<2><<<nodeTiles, 256, smem6>>>(px == px ? pagg : pagg, L, 3 + L,
                                              conv_b1 + L * D, conv_b2 + L * D,
                                              px, out2, nNodes);
    }

    // mean pool + classifier + softmax
    pool_kernel<<<gatherBlocks, 256>>>(batch, nNodes);
    classifier_kernel<<<N_GRAPHS, D>>>(batch, nNodes, mlp_w1, mlp_b1, mlp_w2,
                                       mlp_b2, out);
}

// round 4
// speedup vs baseline: 1.7362x; 1.1778x over previous
#include <cuda_runtime.h>
#include <cuda_bf16.h>
#include <math.h>
#include <stdint.h>

// Problem constants
#define N_NODES   100000
#define N_EDGES   600000
#define N_GRAPHS  1000
#define VOCAB     10000
#define D         128
#define TM        128              // rows per tile
#define ROWB      272              // padded smem row stride in bytes (136 bf16)
#define TILE_B    (128 * ROWB)     // 34816 bytes per 128x128 bf16 tile

// ---------------- scratch -------------------------------------------------
__device__ float g_x[N_NODES * D];
__device__ float g_agg[N_NODES * D];
__device__ float g_embT[VOCAB * D];
__device__ float g_pool[N_GRAPHS * D];
// split-bf16 weights, stored transposed [n][k], linear 128x128
// mats 0..2 = conv_w1[L], 3..5 = conv_w2[L]
__device__ __nv_bfloat16 g_wh[6][D * D];
__device__ __nv_bfloat16 g_wl[6][D * D];

// ---------------- helpers -------------------------------------------------
__device__ __forceinline__ uint32_t smem_u32(const void* p) {
    uint32_t a;
    asm("{ .reg .u64 t; cvta.to.shared.u64 t, %1; cvt.u32.u64 %0, t; }"
        : "=r"(a) : "l"(p));
    return a;
}

__device__ __forceinline__ uint32_t pack_bf16(float a, float b) {
    __nv_bfloat162 t;
    t.x = __float2bfloat16_rn(a);
    t.y = __float2bfloat16_rn(b);
    return *(uint32_t*)&t;
}

__device__ __forceinline__ void mma16816(float* d, uint32_t a0, uint32_t a1,
                                         uint32_t a2, uint32_t a3,
                                         uint32_t b0, uint32_t b1) {
    asm volatile(
        "mma.sync.aligned.m16n8k16.row.col.f32.bf16.bf16.f32 "
        "{%0,%1,%2,%3}, {%4,%5,%6,%7}, {%8,%9}, {%0,%1,%2,%3};\n"
        : "+f"(d[0]), "+f"(d[1]), "+f"(d[2]), "+f"(d[3])
        : "r"(a0), "r"(a1), "r"(a2), "r"(a3), "r"(b0), "r"(b1));
}

__device__ __forceinline__ void ldm_x4(uint32_t& r0, uint32_t& r1, uint32_t& r2,
                                       uint32_t& r3, uint32_t addr) {
    asm volatile("ldmatrix.sync.aligned.m8n8.x4.shared.b16 {%0,%1,%2,%3}, [%4];"
                 : "=r"(r0), "=r"(r1), "=r"(r2), "=r"(r3) : "r"(addr));
}

__device__ __forceinline__ void ldm_x2(uint32_t& r0, uint32_t& r1, uint32_t addr) {
    asm volatile("ldmatrix.sync.aligned.m8n8.x2.shared.b16 {%0,%1}, [%2];"
                 : "=r"(r0), "=r"(r1) : "r"(addr));
}

// ---------------- weight prep: split + transpose ---------------------------
__global__ void prep_weights(const float* __restrict__ w1,
                             const float* __restrict__ w2) {
    int i = blockIdx.x * blockDim.x + threadIdx.x;
    if (i >= 6 * D * D) return;
    int m = i / (D * D), kn = i % (D * D);
    int k = kn / D, n = kn % D;
    float v = (m < 3) ? w1[m * D * D + kn] : w2[(m - 3) * D * D + kn];
    __nv_bfloat16 h = __float2bfloat16_rn(v);
    __nv_bfloat16 l = __float2bfloat16_rn(v - __bfloat162float(h));
    g_wh[m][n * D + k] = h;     // B = W^T : [n][k]
    g_wl[m][n * D + k] = l;
}

// ---------------- zero / gather / scatter ----------------------------------
__global__ void zero_pool_kernel() {
    for (int i = blockIdx.x * blockDim.x + threadIdx.x; i < N_GRAPHS * D;
         i += gridDim.x * blockDim.x)
        g_pool[i] = 0.0f;
}

__global__ void gather_kernel(const int* __restrict__ x_idx, int nNodes) {
    int gid = blockIdx.x * blockDim.x + threadIdx.x;
    int node = gid >> 5, c = gid & 31;
    if (node >= nNodes) return;
    int row = x_idx[node];
    float4 v = ((const float4*)g_embT)[row * 32 + c];
    ((float4*)g_x)[node * 32 + c]   = v;
    ((float4*)g_agg)[node * 32 + c] = v;
}

__global__ void scatter_kernel(const float* __restrict__ xin,
                               float* __restrict__ agg,
                               const int* __restrict__ src,
                               const int* __restrict__ dst, int nE) {
    int gid = blockIdx.x * blockDim.x + threadIdx.x;
    int e = gid >> 5, c = gid & 31;
    if (e >= nE) return;
    int s = src[e], d = dst[e];
    float4 v = ((const float4*)xin)[s * 32 + c];
    float* p = agg + d * D + c * 4;
    asm volatile("red.global.add.v4.f32 [%0], {%1, %2, %3, %4};"
                 :: "l"(p), "f"(v.x), "f"(v.y), "f"(v.z), "f"(v.w)
                 : "memory");
}

// ---------------- GEMM phase: 3-split bf16 via ldmatrix + mma.sync ---------
// Per warp: 64x32 output patch. Addresses are absolute smem byte addresses
// with per-lane offsets already folded in.
__device__ __forceinline__ void gemm_phase(uint32_t aH, uint32_t aL,
                                           uint32_t bH, uint32_t bL,
                                           float (&acc)[4][4][4]) {
#pragma unroll
    for (int k0 = 0; k0 < D; k0 += 16) {
        uint32_t ah0[4], ah1[4], ah2[4], ah3[4];
        uint32_t al0[4], al1[4], al2[4], al3[4];
        uint32_t bh0[4], bh1[4], bl0[4], bl1[4];
#pragma unroll
        for (int mt = 0; mt < 4; ++mt) {
            ldm_x4(ah0[mt], ah1[mt], ah2[mt], ah3[mt], aH + mt * (16 * ROWB) + k0 * 2);
            ldm_x4(al0[mt], al1[mt], al2[mt], al3[mt], aL + mt * (16 * ROWB) + k0 * 2);
        }
#pragma unroll
        for (int nt = 0; nt < 4; ++nt) {
            ldm_x2(bh0[nt], bh1[nt], bH + nt * (8 * ROWB) + k0 * 2);
            ldm_x2(bl0[nt], bl1[nt], bL + nt * (8 * ROWB) + k0 * 2);
        }
#pragma unroll
        for (int mt = 0; mt < 4; ++mt) {
#pragma unroll
            for (int nt = 0; nt < 4; ++nt) {
                mma16816(acc[mt][nt], ah0[mt], ah1[mt], ah2[mt], ah3[mt], bh0[nt], bh1[nt]);
                mma16816(acc[mt][nt], ah0[mt], ah1[mt], ah2[mt], ah3[mt], bl0[nt], bl1[nt]);
                mma16816(acc[mt][nt], al0[mt], al1[mt], al2[mt], al3[mt], bh0[nt], bh1[nt]);
            }
        }
    }
}

// ---------------- persistent fused MLP -------------------------------------
// MODE 0: out = x @ W[w2_id]
// MODE 1: h = relu(x + b1);            out = relu(h @ W[w2_id] + b2)
// MODE 2: h = relu(x @ W[w1_id] + b1); out = relu(h @ W[w2_id] + b2)
// If pbatch != nullptr (final layer): no global out; instead
// red.add relu(h@W2+b2) into g_pool[batch[row]].
template <int MODE>
__global__ void __launch_bounds__(256, 1)
mlp_mma(const float* __restrict__ x, int w1_id, int w2_id,
        const float* __restrict__ b1, const float* __restrict__ b2,
        float* __restrict__ out, float* __restrict__ out2,
        const int* __restrict__ pbatch, int nRows, int nTiles) {
    extern __shared__ __align__(16) unsigned char sm[];
    unsigned char* Ah  = sm;
    unsigned char* Al  = sm + TILE_B;
    unsigned char* W2h = sm + 2 * TILE_B;
    unsigned char* W2l = sm + 3 * TILE_B;
    unsigned char* W1h = sm + 4 * TILE_B;   // MODE 2 only
    unsigned char* W1l = sm + 5 * TILE_B;
    __shared__ float b1s[D], b2s[D];

    const int tid  = threadIdx.x;
    const int lane = tid & 31, wid = tid >> 5;
    const int R0 = (wid >> 2) * 64, N0 = (wid & 3) * 32;

    // biases
    if (MODE != 0 && tid < D) {
        b2s[tid] = b2[tid];
        if (MODE == 2) b1s[tid] = b1[tid];
    }

    // stage weights once (pad 256B rows to 272B stride)
    {
        const uint4* s2h = (const uint4*)g_wh[w2_id];
        const uint4* s2l = (const uint4*)g_wl[w2_id];
        for (int i = tid; i < 128 * 16; i += 256) {
            int n = i >> 4, c = i & 15;
            *(uint4*)(W2h + n * ROWB + c * 16) = s2h[n * 16 + c];
            *(uint4*)(W2l + n * ROWB + c * 16) = s2l[n * 16 + c];
        }
        if (MODE == 2) {
            const uint4* s1h = (const uint4*)g_wh[w1_id];
            const uint4* s1l = (const uint4*)g_wl[w1_id];
            for (int i = tid; i < 128 * 16; i += 256) {
                int n = i >> 4, c = i & 15;
                *(uint4*)(W1h + n * ROWB + c * 16) = s1h[n * 16 + c];
                *(uint4*)(W1l + n * ROWB + c * 16) = s1l[n * 16 + c];
            }
        }
    }

    // per-lane ldmatrix address offsets
    const uint32_t aOff = (uint32_t)(R0 + (lane & 15)) * ROWB + ((lane >> 4) * 16);
    const uint32_t bOff = (uint32_t)(N0 + (lane & 7)) * ROWB + (((lane >> 3) & 1) * 16);
    const uint32_t aH = smem_u32(Ah) + aOff, aL = smem_u32(Al) + aOff;
    const uint32_t w2H = smem_u32(W2h) + bOff, w2L = smem_u32(W2l) + bOff;
    const uint32_t w1H = (MODE == 2) ? smem_u32(W1h) + bOff : 0;
    const uint32_t w1L = (MODE == 2) ? smem_u32(W1l) + bOff : 0;

    for (int t = blockIdx.x; t < nTiles; t += gridDim.x) {
        const int row0 = t * TM;
        __syncthreads();    // protect smem A from previous tile's readers

        // ---- load + split-convert A tile ----
        for (int i = tid; i < TM * 32; i += 256) {
            int r = i >> 5, c4 = (i & 31) * 4;
            int gr = row0 + r;
            float4 v = make_float4(0.f, 0.f, 0.f, 0.f);
            if (gr < nRows) v = *(const float4*)(x + (size_t)gr * D + c4);
            if (MODE == 1) {
                float4 bv = *(const float4*)(b1 + c4);
                v.x = fmaxf(v.x + bv.x, 0.f); v.y = fmaxf(v.y + bv.y, 0.f);
                v.z = fmaxf(v.z + bv.z, 0.f); v.w = fmaxf(v.w + bv.w, 0.f);
            }
            uint32_t h01 = pack_bf16(v.x, v.y), h23 = pack_bf16(v.z, v.w);
            float f0 = __uint_as_float(h01 << 16);
            float f1 = __uint_as_float(h01 & 0xffff0000u);
            float f2 = __uint_as_float(h23 << 16);
            float f3 = __uint_as_float(h23 & 0xffff0000u);
            uint32_t l01 = pack_bf16(v.x - f0, v.y - f1);
            uint32_t l23 = pack_bf16(v.z - f2, v.w - f3);
            *(uint2*)(Ah + r * ROWB + c4 * 2) = make_uint2(h01, h23);
            *(uint2*)(Al + r * ROWB + c4 * 2) = make_uint2(l01, l23);
        }
        __syncthreads();

        float acc[4][4][4];

        if (MODE == 2) {
            // phase 1: h = relu(x @ W1 + b1) -> back into Ah/Al
#pragma unroll
            for (int nt = 0; nt < 4; ++nt) {
                int c = N0 + nt * 8 + (lane & 3) * 2;
                float bb0 = b1s[c], bb1 = b1s[c + 1];
#pragma unroll
                for (int mt = 0; mt < 4; ++mt) {
                    acc[mt][nt][0] = bb0; acc[mt][nt][1] = bb1;
                    acc[mt][nt][2] = bb0; acc[mt][nt][3] = bb1;
                }
            }
            gemm_phase(aH, aL, w1H, w1L, acc);
            __syncthreads();
#pragma unroll
            for (int mt = 0; mt < 4; ++mt) {
#pragma unroll
                for (int nt = 0; nt < 4; ++nt) {
                    int r = R0 + mt * 16 + (lane >> 2);
                    int c = N0 + nt * 8 + (lane & 3) * 2;
                    float v0 = fmaxf(acc[mt][nt][0], 0.f), v1 = fmaxf(acc[mt][nt][1], 0.f);
                    float v2 = fmaxf(acc[mt][nt][2], 0.f), v3 = fmaxf(acc[mt][nt][3], 0.f);
                    uint32_t h01 = pack_bf16(v0, v1), h23 = pack_bf16(v2, v3);
                    float f0 = __uint_as_float(h01 << 16);
                    float f1 = __uint_as_float(h01 & 0xffff0000u);
                    float f2 = __uint_as_float(h23 << 16);
                    float f3 = __uint_as_float(h23 & 0xffff0000u);
                    *(uint32_t*)(Ah + r * ROWB + c * 2)       = h01;
                    *(uint32_t*)(Ah + (r + 8) * ROWB + c * 2) = h23;
                    *(uint32_t*)(Al + r * ROWB + c * 2)       = pack_bf16(v0 - f0, v1 - f1);
                    *(uint32_t*)(Al + (r + 8) * ROWB + c * 2) = pack_bf16(v2 - f2, v3 - f3);
                }
            }
            __syncthreads();
        }

        // phase 2: out = (relu)(h @ W2 + b2)
        if (MODE == 0) {
#pragma unroll
            for (int mt = 0; mt < 4; ++mt)
#pragma unroll
                for (int nt = 0; nt < 4; ++nt)
                    acc[mt][nt][0] = acc[mt][nt][1] = acc[mt][nt][2] = acc[mt][nt][3] = 0.f;
        } else {
#pragma unroll
            for (int nt = 0; nt < 4; ++nt) {
                int c = N0 + nt * 8 + (lane & 3) * 2;
                float bb0 = b2s[c], bb1 = b2s[c + 1];
#pragma unroll
                for (int mt = 0; mt < 4; ++mt) {
                    acc[mt][nt][0] = bb0; acc[mt][nt][1] = bb1;
                    acc[mt][nt][2] = bb0; acc[mt][nt][3] = bb1;
                }
            }
        }
        gemm_phase(aH, aL, w2H, w2L, acc);

        // ---- epilogue ----
#pragma unroll
        for (int mt = 0; mt < 4; ++mt) {
            int r = row0 + R0 + mt * 16 + (lane >> 2);
            int bi0 = 0, bi8 = 0;
            if (pbatch) {
                if (r < nRows)     bi0 = pbatch[r];
                if (r + 8 < nRows) bi8 = pbatch[r + 8];
            }
#pragma unroll
            for (int nt = 0; nt < 4; ++nt) {
                int c = N0 + nt * 8 + (lane & 3) * 2;
                float v0 = acc[mt][nt][0], v1 = acc[mt][nt][1];
                float v2 = acc[mt][nt][2], v3 = acc[mt][nt][3];
                if (MODE != 0) {
                    v0 = fmaxf(v0, 0.f); v1 = fmaxf(v1, 0.f);
                    v2 = fmaxf(v2, 0.f); v3 = fmaxf(v3, 0.f);
                }
                if (pbatch) {
                    if (r < nRows) {
                        float* p = g_pool + bi0 * D + c;
                        asm volatile("red.global.add.v2.f32 [%0], {%1, %2};"
                                     :: "l"(p), "f"(v0), "f"(v1) : "memory");
                    }
                    if (r + 8 < nRows) {
                        float* p = g_pool + bi8 * D + c;
                        asm volatile("red.global.add.v2.f32 [%0], {%1, %2};"
                                     :: "l"(p), "f"(v2), "f"(v3) : "memory");
                    }
                } else {
                    if (r < nRows) {
                        *(float2*)(out + (size_t)r * D + c) = make_float2(v0, v1);
                        if (out2) *(float2*)(out2 + (size_t)r * D + c) = make_float2(v0, v1);
                    }
                    if (r + 8 < nRows) {
                        *(float2*)(out + (size_t)(r + 8) * D + c) = make_float2(v2, v3);
                        if (out2) *(float2*)(out2 + (size_t)(r + 8) * D + c) = make_float2(v2, v3);
                    }
                }
            }
        }
    }
}

// ---------------- classifier -----------------------------------------------
__global__ void classifier_kernel(const int* __restrict__ batch, int nNodes,
                                  const float* __restrict__ w1,
                                  const float* __restrict__ b1,
                                  const float* __restrict__ w2,
                                  const float* __restrict__ b2,
                                  float* __restrict__ out) {
    __shared__ float gs[D];
    __shared__ float hs[64];
    __shared__ float cnt_s;
    const int b = blockIdx.x;
    const int t = threadIdx.x;

    if (t == 0) {
        int lo = 0, hi = nNodes;
        while (lo < hi) { int m = (lo + hi) >> 1; if (batch[m] < b) lo = m + 1; else hi = m; }
        int start = lo;
        lo = start; hi = nNodes;
        while (lo < hi) { int m = (lo + hi) >> 1; if (batch[m] <= b) lo = m + 1; else hi = m; }
        cnt_s = fmaxf((float)(lo - start), 1.0f);
    }
    __syncthreads();

    gs[t] = g_pool[b * D + t] / cnt_s;
    __syncthreads();

    if (t < 64) {
        float h = b1[t];
#pragma unroll 8
        for (int k = 0; k < D; ++k) h += gs[k] * w1[k * 64 + t];
        hs[t] = fmaxf(h, 0.f);
    }
    __syncthreads();

    if (t == 0) {
        float o0 = b2[0], o1 = b2[1];
#pragma unroll 8
        for (int j = 0; j < 64; ++j) {
            o0 += hs[j] * w2[2 * j];
            o1 += hs[j] * w2[2 * j + 1];
        }
        float m = fmaxf(o0, o1);
        float e0 = expf(o0 - m), e1 = expf(o1 - m);
        float s = e0 + e1;
        out[2 * b]     = e0 / s;
        out[2 * b + 1] = e1 / s;
    }
}

// ---------------------------------------------------------------------------
extern "C" void kernel_launch(void* const* d_in, const int* in_sizes, int n_in,
                              void* d_out, int out_size) {
    const int*   x_idx   = (const int*)d_in[0];
    const int*   edge    = (const int*)d_in[1];
    const int*   batch   = (const int*)d_in[2];
    const float* emb     = (const float*)d_in[3];
    const float* conv_w1 = (const float*)d_in[4];
    const float* conv_b1 = (const float*)d_in[5];
    const float* conv_w2 = (const float*)d_in[6];
    const float* conv_b2 = (const float*)d_in[7];
    const float* mlp_w1  = (const float*)d_in[8];
    const float* mlp_b1  = (const float*)d_in[9];
    const float* mlp_w2  = (const float*)d_in[10];
    const float* mlp_b2  = (const float*)d_in[11];
    float* out = (float*)d_out;

    const int nNodes = in_sizes[0];
    const int nEdges = in_sizes[1] / 2;
    const int nVocab = in_sizes[3] / D;
    const int* src = edge;
    const int* dst = edge + nEdges;

    float *px, *pagg, *pembT;
    cudaGetSymbolAddress((void**)&px,    g_x);
    cudaGetSymbolAddress((void**)&pagg,  g_agg);
    cudaGetSymbolAddress((void**)&pembT, g_embT);

    const int smem_small = 4 * TILE_B;   // 139264
    const int smem_big   = 6 * TILE_B;   // 208896
    cudaFuncSetAttribute(mlp_mma<0>, cudaFuncAttributeMaxDynamicSharedMemorySize, smem_small);
    cudaFuncSetAttribute(mlp_mma<1>, cudaFuncAttributeMaxDynamicSharedMemorySize, smem_small);
    cudaFuncSetAttribute(mlp_mma<2>, cudaFuncAttributeMaxDynamicSharedMemorySize, smem_big);

    const int nodeTiles = (nNodes + TM - 1) / TM;
    const int embTiles  = (nVocab + TM - 1) / TM;
    const int gatherBlocks  = (nNodes * 32 + 255) / 256;
    const int scatterBlocks = (nEdges * 32 + 255) / 256;
    const int grid1 = nodeTiles < 148 ? nodeTiles : 148;
    const int gridE = embTiles  < 148 ? embTiles  : 148;

    zero_pool_kernel<<<500, 256>>>();
    prep_weights<<<(6 * D * D + 255) / 256, 256>>>(conv_w1, conv_w2);

    // embT = emb @ conv_w1[0]
    mlp_mma<0><<<gridE, 256, smem_small>>>(emb, -1, 0, nullptr, nullptr,
                                           pembT, nullptr, nullptr, nVocab, embTiles);

    // layer 0
    gather_kernel<<<gatherBlocks, 256>>>(x_idx, nNodes);
    scatter_kernel<<<scatterBlocks, 256>>>(px, pagg, src, dst, nEdges);
    mlp_mma<1><<<grid1, 256, smem_small>>>(pagg, -1, 3, conv_b1, conv_b2,
                                           px, pagg, nullptr, nNodes, nodeTiles);

    // layer 1
    scatter_kernel<<<scatterBlocks, 256>>>(px, pagg, src, dst, nEdges);
    mlp_mma<2><<<grid1, 256, smem_big>>>(pagg, 1, 4, conv_b1 + D, conv_b2 + D,
                                         px, pagg, nullptr, nNodes, nodeTiles);

    // layer 2 (fused mean-pool accumulation)
    scatter_kernel<<<scatterBlocks, 256>>>(px, pagg, src, dst, nEdges);
    mlp_mma<2><<<grid1, 256, smem_big>>>(pagg, 2, 5, conv_b1 + 2 * D, conv_b2 + 2 * D,
                                         nullptr, nullptr, batch, nNodes, nodeTiles);

    // classifier + softmax
    classifier_kernel<<<N_GRAPHS, D>>>(batch, nNodes, mlp_w1, mlp_b1, mlp_w2,
                                       mlp_b2, out);
}